// round 15
// baseline (speedup 1.0000x reference)
#include <cuda_runtime.h>

// MeshfreeKANNet: u[m] = (sum_n phi_win[m,n]*w[n]) / (sum_n phi_win[m,n] + 1e-10)
// R15 = R11 (best: 14.4us) + spatial binning pre-pass.
//  Kernel A: bin 1024 nodes into a 7x7 grid of 0.3-cells (cell-major,
//            node-index order within cell -> deterministic). 49 blocks x 1 warp.
//  Kernel B: warp per point; phase-1 scans only the 3x3 cell neighborhood
//            (~170 nodes vs 1024, 6 ballot iters vs 32); phase-2 is R11's
//            ILP-2 pair pipeline with bit-exact reference math.

#define MM      4096
#define NN      1024
#define HIDN    8
#define WARPS   8
#define THREADS 256
#define BLOCKS  (MM / WARPS)

#define CELLS   7
#define NCELL   (CELLS * CELLS)
#define INV_CS  (1.0f / 0.3f)      // cell size 0.3 over [-1, 1.1)

#define R2_F     0.09f
#define INV_R    (1.0f / 0.3f)
#define INV_H    (1.0f / 0.75f)

typedef float4 f4;

__device__ float2 g_bxy[NN];       // binned node coords
__device__ float  g_bw [NN];       // binned node weights
__device__ int    g_off[NCELL + 1];

// ---- Kernel A: deterministic node binning (block c owns cell c) ----
__global__ void bin_kernel(const float* __restrict__ nodes,
                           const float* __restrict__ w)
{
    const int c    = blockIdx.x;       // 0..48
    const int lane = threadIdx.x;      // 32 threads
    const unsigned lmask = (1u << lane) - 1u;

    // pass 1: count nodes in cells < c (global write offset)
    int nlt = 0;
    for (int base = 0; base < NN; base += 32) {
        const int n = base + lane;
        const float2 nd = ((const float2*)nodes)[n];
        int cx = (int)floorf((nd.x + 1.0f) * INV_CS);
        int cy = (int)floorf((nd.y + 1.0f) * INV_CS);
        cx = min(max(cx, 0), CELLS - 1);
        cy = min(max(cy, 0), CELLS - 1);
        const int cell = cy * CELLS + cx;
        nlt += __popc(__ballot_sync(0xffffffffu, cell < c));
    }
    if (lane == 0) {
        g_off[c] = nlt;
        if (c == 0) g_off[NCELL] = NN;   // all nodes are binned (clamped)
    }

    // pass 2: compact this cell's nodes in node-index order
    int cnt = 0;
    for (int base = 0; base < NN; base += 32) {
        const int n = base + lane;
        const float2 nd = ((const float2*)nodes)[n];
        int cx = (int)floorf((nd.x + 1.0f) * INV_CS);
        int cy = (int)floorf((nd.y + 1.0f) * INV_CS);
        cx = min(max(cx, 0), CELLS - 1);
        cy = min(max(cy, 0), CELLS - 1);
        const bool mine = (cy * CELLS + cx) == c;
        const unsigned msk = __ballot_sync(0xffffffffu, mine);
        if (mine) {
            const int pos = nlt + cnt + __popc(msk & lmask);
            g_bxy[pos] = nd;
            g_bw [pos] = w[n];
        }
        cnt += __popc(msk);
    }
}

// One pair's KAN evaluation. Bit-exact reference math (R5/R11 form).
__device__ __forceinline__ float pair_phi(float dx, float dy,
                                          const f4 (*s_Wp)[4])
{
    const float gridv[5] = {-1.5f, -0.75f, 0.0f, 0.75f, 1.5f};
    const float d2 = fmaf(dx, dx, dy * dy);
    const float kx = dx * INV_R;
    const float ky = dy * INV_R;

    float ba[5], bb[5];
    #pragma unroll
    for (int s = 0; s < 5; s++) {
        ba[s] = fmaxf(0.0f, 1.0f - fabsf(kx - gridv[s]) * INV_H);
        bb[s] = fmaxf(0.0f, 1.0f - fabsf(ky - gridv[s]) * INV_H);
    }

    float phi_raw = 0.0f;
    #pragma unroll 2
    for (int h = 0; h < HIDN; h++) {
        const f4 q0 = s_Wp[h][0];
        const f4 q1 = s_Wp[h][1];
        const f4 q2 = s_Wp[h][2];
        const f4 q3 = s_Wp[h][3];
        const float wa[5]  = {q0.x, q0.y, q0.z, q0.w, q1.x};
        const float wb[5]  = {q1.y, q1.z, q1.w, q2.x, q2.y};
        const float w2r[5] = {q2.z, q2.w, q3.x, q3.y, q3.z};

        float hv = 0.0f;
        #pragma unroll
        for (int s = 0; s < 5; s++) {
            hv = fmaf(ba[s], wa[s], hv);
            hv = fmaf(bb[s], wb[s], hv);
        }
        #pragma unroll
        for (int s = 0; s < 5; s++) {
            const float bh = fmaxf(0.0f, 1.0f - fabsf(hv - gridv[s]) * INV_H);
            phi_raw = fmaf(bh, w2r[s], phi_raw);
        }
    }

    const float q = sqrtf(d2) * INV_R;
    const float win = fmaf(q * q, fmaf(fmaf(-3.0f, q, 8.0f), q, -6.0f), 1.0f);
    return phi_raw * win;
}

// ---- Kernel B: main evaluation ----
__global__ __launch_bounds__(THREADS, 4)
void meshfree_kan_kernel(const float* __restrict__ x,
                         float* __restrict__ out)
{
    __shared__ f4 s_Wp[HIDN][4];   // filled from g_* copies below
    __shared__ unsigned short s_buf[WARPS][256];

    // weights come in via constant-ish global pointers stored by launch
    extern __shared__ char dummy[];  // (unused; static smem only)

    const int tid = threadIdx.x;
    const int warp = tid >> 5;
    const int lane = tid & 31;
    const int m = blockIdx.x * WARPS + warp;

    // stash W pointers via grid constants: passed through g_Wsrc (set below)
    // (filled at the bottom of the file)
    extern __device__ const float* g_Wsrc[3];
    if (tid < HIDN * 16) {
        const int h = tid >> 4;
        const int e = tid & 15;
        float v = 0.0f;
        if (e < 5)       v = g_Wsrc[0][h * 5 + e];
        else if (e < 10) v = g_Wsrc[1][h * 5 + (e - 5)];
        else if (e < 15) v = g_Wsrc[2][h * 5 + (e - 10)];
        ((float*)s_Wp)[tid] = v;
    }
    __syncthreads();

    const float px = x[2 * m];
    const float py = x[2 * m + 1];

    // ---- Phase 1: scan 3x3 cell neighborhood, ballot-compact hits ----
    int cx = (int)floorf((px + 1.0f) * INV_CS);
    int cy = (int)floorf((py + 1.0f) * INV_CS);
    cx = min(max(cx, 0), CELLS - 1);
    cy = min(max(cy, 0), CELLS - 1);
    const int x0 = max(cx - 1, 0), x1 = min(cx + 1, CELLS - 1);
    const int y0 = max(cy - 1, 0), y1 = min(cy + 1, CELLS - 1);

    int cnt = 0;
    const unsigned lmask = (1u << lane) - 1u;
    for (int ry = y0; ry <= y1; ry++) {
        const int s0 = __ldg(&g_off[ry * CELLS + x0]);
        const int e0 = __ldg(&g_off[ry * CELLS + x1 + 1]);
        for (int base = s0; base < e0; base += 32) {
            const int b  = base + lane;
            const int bc = min(b, NN - 1);
            const float2 nd = __ldg(&g_bxy[bc]);
            const float dx = px - nd.x;
            const float dy = py - nd.y;
            const float d2 = fmaf(dx, dx, dy * dy);
            const bool hit = (b < e0) && (d2 <= R2_F);
            const unsigned msk = __ballot_sync(0xffffffffu, hit);
            if (hit) s_buf[warp][cnt + __popc(msk & lmask)] = (unsigned short)b;
            cnt += __popc(msk);
        }
    }
    __syncwarp();

    // ---- Phase 2: two independent pair pipelines per lane (R11 form) ----
    float S = 0.0f, Sw = 0.0f;
    for (int i = lane; i < cnt; i += 64) {
        const int iB = i + 32;
        const bool hasB = (iB < cnt);

        const int bA = (int)s_buf[warp][i];
        const float2 ndA = __ldg(&g_bxy[bA]);
        const float phiA = pair_phi(px - ndA.x, py - ndA.y, s_Wp);

        float phiB = 0.0f;
        int bB = 0;
        if (hasB) {
            bB = (int)s_buf[warp][iB];
            const float2 ndB = __ldg(&g_bxy[bB]);
            phiB = pair_phi(px - ndB.x, py - ndB.y, s_Wp);
        }

        S  += phiA;
        Sw  = fmaf(phiA, __ldg(&g_bw[bA]), Sw);
        if (hasB) {
            S  += phiB;
            Sw  = fmaf(phiB, __ldg(&g_bw[bB]), Sw);
        }
    }

    // ---- Warp reduction + normalize ----
    #pragma unroll
    for (int o = 16; o > 0; o >>= 1) {
        S  += __shfl_xor_sync(0xffffffffu, S,  o);
        Sw += __shfl_xor_sync(0xffffffffu, Sw, o);
    }
    if (lane == 0) out[m] = Sw / (S + 1e-10f);
}

__device__ const float* g_Wsrc[3];

__global__ void set_wsrc_kernel(const float* a, const float* b, const float* c)
{
    g_Wsrc[0] = a; g_Wsrc[1] = b; g_Wsrc[2] = c;
}

extern "C" void kernel_launch(void* const* d_in, const int* in_sizes, int n_in,
                              void* d_out, int out_size)
{
    const float* x     = (const float*)d_in[0];   // [4096, 2]
    const float* nodes = (const float*)d_in[1];   // [1024, 2]
    const float* W1a   = (const float*)d_in[2];   // [8, 5]
    const float* W1b   = (const float*)d_in[3];   // [8, 5]
    const float* W2    = (const float*)d_in[4];   // [1, 40]
    const float* w     = (const float*)d_in[5];   // [1024, 1]
    float* out = (float*)d_out;                   // [4096, 1]

    set_wsrc_kernel<<<1, 1>>>(W1a, W1b, W2);
    bin_kernel<<<NCELL, 32>>>(nodes, w);
    meshfree_kan_kernel<<<BLOCKS, THREADS>>>(x, out);
}

// round 16
// speedup vs baseline: 1.1657x; 1.1657x over previous
#include <cuda_runtime.h>

// MeshfreeKANNet: u[m] = (sum_n phi_win[m,n]*w[n]) / (sum_n phi_win[m,n] + 1e-10)
// R16: single-launch fused version of R15 (launch overhead ~3.5us/kernel!).
//  * Blocks 0..48 bin the 1024 nodes into a 7x7 grid of 0.3-cells (one cell
//    per block, 8 warps split the scan; deterministic node-index order).
//  * Software release/acquire flag (threadfence + atomic arrive, volatile
//    spin). Binning blocks are wave-1 scheduled -> no deadlock at any
//    occupancy. Counters self-reset for graph replay.
//  * Phase-1 scans only the 3x3 cell neighborhood (~200 nodes vs 1024).
//  * Phase-2 = R11 ILP-2 pair pipeline, bit-exact reference math.

#define MM      4096
#define NN      1024
#define HIDN    8
#define WARPS   8
#define THREADS 256
#define BLOCKS  (MM / WARPS)

#define CELLS   7
#define NCELL   (CELLS * CELLS)
#define INV_CS  (1.0f / 0.3f)

#define R2_F     0.09f
#define INV_R    (1.0f / 0.3f)
#define INV_H    (1.0f / 0.75f)

typedef float4 f4;

__device__ float2   g_bxy[NN];
__device__ float    g_bw [NN];
__device__ int      g_off[NCELL + 1];
__device__ unsigned g_arrive;   // zero-init; reset at end of each run
__device__ unsigned g_done;

__device__ __forceinline__ int node_cell(float2 nd)
{
    int cx = (int)floorf((nd.x + 1.0f) * INV_CS);
    int cy = (int)floorf((nd.y + 1.0f) * INV_CS);
    cx = min(max(cx, 0), CELLS - 1);
    cy = min(max(cy, 0), CELLS - 1);
    return cy * CELLS + cx;
}

// One pair's KAN evaluation. Bit-exact reference math (R5/R11 form).
__device__ __forceinline__ float pair_phi(float dx, float dy,
                                          const f4 (*s_Wp)[4])
{
    const float gridv[5] = {-1.5f, -0.75f, 0.0f, 0.75f, 1.5f};
    const float d2 = fmaf(dx, dx, dy * dy);
    const float kx = dx * INV_R;
    const float ky = dy * INV_R;

    float ba[5], bb[5];
    #pragma unroll
    for (int s = 0; s < 5; s++) {
        ba[s] = fmaxf(0.0f, 1.0f - fabsf(kx - gridv[s]) * INV_H);
        bb[s] = fmaxf(0.0f, 1.0f - fabsf(ky - gridv[s]) * INV_H);
    }

    float phi_raw = 0.0f;
    #pragma unroll 2
    for (int h = 0; h < HIDN; h++) {
        const f4 q0 = s_Wp[h][0];
        const f4 q1 = s_Wp[h][1];
        const f4 q2 = s_Wp[h][2];
        const f4 q3 = s_Wp[h][3];
        const float wa[5]  = {q0.x, q0.y, q0.z, q0.w, q1.x};
        const float wb[5]  = {q1.y, q1.z, q1.w, q2.x, q2.y};
        const float w2r[5] = {q2.z, q2.w, q3.x, q3.y, q3.z};

        float hv = 0.0f;
        #pragma unroll
        for (int s = 0; s < 5; s++) {
            hv = fmaf(ba[s], wa[s], hv);
            hv = fmaf(bb[s], wb[s], hv);
        }
        #pragma unroll
        for (int s = 0; s < 5; s++) {
            const float bh = fmaxf(0.0f, 1.0f - fabsf(hv - gridv[s]) * INV_H);
            phi_raw = fmaf(bh, w2r[s], phi_raw);
        }
    }

    const float q = sqrtf(d2) * INV_R;
    const float win = fmaf(q * q, fmaf(fmaf(-3.0f, q, 8.0f), q, -6.0f), 1.0f);
    return phi_raw * win;
}

__global__ __launch_bounds__(THREADS, 4)
void meshfree_kan_kernel(const float* __restrict__ x,
                         const float* __restrict__ nodes,
                         const float* __restrict__ W1a,
                         const float* __restrict__ W1b,
                         const float* __restrict__ W2,
                         const float* __restrict__ w,
                         float* __restrict__ out)
{
    __shared__ f4  s_Wp[HIDN][4];   // {W1a[h][0..4], W1b[h][0..4], W2[h][0..4], 0}
    __shared__ unsigned short s_buf[WARPS][256];
    __shared__ int s_lt[WARPS], s_eq[WARPS];

    const int tid  = threadIdx.x;
    const int warp = tid >> 5;
    const int lane = tid & 31;
    const unsigned lmask = (1u << lane) - 1u;

    if (tid < HIDN * 16) {
        const int h = tid >> 4;
        const int e = tid & 15;
        float v = 0.0f;
        if (e < 5)       v = W1a[h * 5 + e];
        else if (e < 10) v = W1b[h * 5 + (e - 5)];
        else if (e < 15) v = W2 [h * 5 + (e - 10)];
        ((float*)s_Wp)[tid] = v;
    }

    // ================= Binning: blocks 0..48, one cell each =================
    if (blockIdx.x < NCELL) {
        const int c  = blockIdx.x;
        const int b0 = warp * (NN / WARPS);           // 128-node slice
        const int b1 = b0 + (NN / WARPS);

        // pass A: per-warp counts of cell<c and cell==c in this slice
        int clt = 0, ceq = 0;
        for (int base = b0; base < b1; base += 32) {
            const int n = base + lane;
            const float2 nd = ((const float2*)nodes)[n];
            const int cell = node_cell(nd);
            clt += __popc(__ballot_sync(0xffffffffu, cell < c));
            ceq += __popc(__ballot_sync(0xffffffffu, cell == c));
        }
        if (lane == 0) { s_lt[warp] = clt; s_eq[warp] = ceq; }
        __syncthreads();

        int nlt = 0;
        #pragma unroll
        for (int k = 0; k < WARPS; k++) nlt += s_lt[k];
        int eqp = 0;
        for (int k = 0; k < warp; k++) eqp += s_eq[k];

        if (tid == 0) {
            g_off[c] = nlt;
            if (c == 0) g_off[NCELL] = NN;
        }

        // pass B: scatter this slice's cell-c nodes (node-index order)
        int cnt = 0;
        for (int base = b0; base < b1; base += 32) {
            const int n = base + lane;
            const float2 nd = ((const float2*)nodes)[n];
            const bool mine = (node_cell(nd) == c);
            const unsigned msk = __ballot_sync(0xffffffffu, mine);
            if (mine) {
                const int pos = nlt + eqp + cnt + __popc(msk & lmask);
                g_bxy[pos] = nd;
                g_bw [pos] = w[n];
            }
            cnt += __popc(msk);
        }
        __threadfence();
        __syncthreads();
        if (tid == 0) atomicAdd(&g_arrive, 1u);
    }

    // ================= Acquire: wait for all 49 cells ================
    if (tid == 0) {
        while (*(volatile unsigned*)&g_arrive < (unsigned)NCELL) { }
    }
    __syncthreads();
    __threadfence();

    // ================= Main evaluation: warp per point ================
    const int m = blockIdx.x * WARPS + warp;
    const float px = x[2 * m];
    const float py = x[2 * m + 1];

    int pcx = (int)floorf((px + 1.0f) * INV_CS);
    int pcy = (int)floorf((py + 1.0f) * INV_CS);
    pcx = min(max(pcx, 0), CELLS - 1);
    pcy = min(max(pcy, 0), CELLS - 1);
    const int x0 = max(pcx - 1, 0), x1 = min(pcx + 1, CELLS - 1);
    const int y0 = max(pcy - 1, 0), y1 = min(pcy + 1, CELLS - 1);

    // ---- Phase 1: scan 3x3 cell neighborhood, ballot-compact hits ----
    int cnt = 0;
    for (int ry = y0; ry <= y1; ry++) {
        const int s0 = g_off[ry * CELLS + x0];
        const int e0 = g_off[ry * CELLS + x1 + 1];
        for (int base = s0; base < e0; base += 32) {
            const int b  = base + lane;
            const int bc = min(b, NN - 1);
            const float2 nd = g_bxy[bc];
            const float dx = px - nd.x;
            const float dy = py - nd.y;
            const float d2 = fmaf(dx, dx, dy * dy);
            const bool hit = (b < e0) && (d2 <= R2_F);
            const unsigned msk = __ballot_sync(0xffffffffu, hit);
            if (hit) s_buf[warp][cnt + __popc(msk & lmask)] = (unsigned short)b;
            cnt += __popc(msk);
        }
    }
    __syncwarp();

    // ---- Phase 2: two independent pair pipelines per lane (R11 form) ----
    float S = 0.0f, Sw = 0.0f;
    for (int i = lane; i < cnt; i += 64) {
        const int iB = i + 32;
        const bool hasB = (iB < cnt);

        const int bA = (int)s_buf[warp][i];
        const float2 ndA = g_bxy[bA];
        const float phiA = pair_phi(px - ndA.x, py - ndA.y, s_Wp);

        float phiB = 0.0f;
        int bB = 0;
        if (hasB) {
            bB = (int)s_buf[warp][iB];
            const float2 ndB = g_bxy[bB];
            phiB = pair_phi(px - ndB.x, py - ndB.y, s_Wp);
        }

        S  += phiA;
        Sw  = fmaf(phiA, g_bw[bA], Sw);
        if (hasB) {
            S  += phiB;
            Sw  = fmaf(phiB, g_bw[bB], Sw);
        }
    }

    // ---- Warp reduction + normalize ----
    #pragma unroll
    for (int o = 16; o > 0; o >>= 1) {
        S  += __shfl_xor_sync(0xffffffffu, S,  o);
        Sw += __shfl_xor_sync(0xffffffffu, Sw, o);
    }
    if (lane == 0) out[m] = Sw / (S + 1e-10f);

    // ---- Reset counters for the next graph replay (last block) ----
    __syncthreads();
    if (tid == 0) {
        const unsigned d = atomicAdd(&g_done, 1u);
        if (d == (unsigned)(BLOCKS - 1)) {
            *(volatile unsigned*)&g_arrive = 0u;
            *(volatile unsigned*)&g_done   = 0u;
            __threadfence();
        }
    }
}

extern "C" void kernel_launch(void* const* d_in, const int* in_sizes, int n_in,
                              void* d_out, int out_size)
{
    const float* x     = (const float*)d_in[0];   // [4096, 2]
    const float* nodes = (const float*)d_in[1];   // [1024, 2]
    const float* W1a   = (const float*)d_in[2];   // [8, 5]
    const float* W1b   = (const float*)d_in[3];   // [8, 5]
    const float* W2    = (const float*)d_in[4];   // [1, 40]
    const float* w     = (const float*)d_in[5];   // [1024, 1]
    float* out = (float*)d_out;                   // [4096, 1]

    meshfree_kan_kernel<<<BLOCKS, THREADS>>>(x, nodes, W1a, W1b, W2, w, out);
}

// round 17
// speedup vs baseline: 1.2944x; 1.1104x over previous
#include <cuda_runtime.h>

// MeshfreeKANNet: u[m] = (sum_n phi_win[m,n]*w[n]) / (sum_n phi_win[m,n] + 1e-10)
// R17: 2 warps per point with MERGED hit-list consumption.
//  * R12 failed because each half-warp consumed its own ~36-hit list
//    (4 pipeline passes/point vs R11's 3). Here the two warps scan disjoint
//    512-node halves (16 ballot iters each, exact split), then jointly walk
//    the concatenated list with stride-64 interleave -> 3 passes/point total,
//    same issued work as R11, spread over 2x the warps (8192 vs 4096).
//  * Nodes/w (12KB read-only) via __ldg -> L1-cached; no smem fill tax.
//  * Per-pair math = bit-exact R5/R11 pair_phi; only outer-sum grouping
//    changes (warp0+warp1 partials per point; safe class, ~5e-5).

#define MM      4096
#define NN      1024
#define HIDN    8
#define WARPS   8
#define THREADS 256
#define PPB     4                  // points per block (2 warps each)
#define BLOCKS  (MM / PPB)         // 1024
#define NH      (NN / 2)           // nodes per scanning warp
#define BUFCAP  256                // per half-list capacity (hits ~36, max ~60)

#define R2_F     0.09f
#define INV_R    (1.0f / 0.3f)
#define INV_H    (1.0f / 0.75f)

typedef float4 f4;

// One pair's KAN evaluation. Bit-exact reference math (R5/R11 form).
__device__ __forceinline__ float pair_phi(float dx, float dy,
                                          const f4 (*s_Wp)[4])
{
    const float gridv[5] = {-1.5f, -0.75f, 0.0f, 0.75f, 1.5f};
    const float d2 = fmaf(dx, dx, dy * dy);
    const float kx = dx * INV_R;
    const float ky = dy * INV_R;

    float ba[5], bb[5];
    #pragma unroll
    for (int s = 0; s < 5; s++) {
        ba[s] = fmaxf(0.0f, 1.0f - fabsf(kx - gridv[s]) * INV_H);
        bb[s] = fmaxf(0.0f, 1.0f - fabsf(ky - gridv[s]) * INV_H);
    }

    float phi_raw = 0.0f;
    #pragma unroll 2
    for (int h = 0; h < HIDN; h++) {
        const f4 q0 = s_Wp[h][0];
        const f4 q1 = s_Wp[h][1];
        const f4 q2 = s_Wp[h][2];
        const f4 q3 = s_Wp[h][3];
        const float wa[5]  = {q0.x, q0.y, q0.z, q0.w, q1.x};
        const float wb[5]  = {q1.y, q1.z, q1.w, q2.x, q2.y};
        const float w2r[5] = {q2.z, q2.w, q3.x, q3.y, q3.z};

        float hv = 0.0f;
        #pragma unroll
        for (int s = 0; s < 5; s++) {
            hv = fmaf(ba[s], wa[s], hv);
            hv = fmaf(bb[s], wb[s], hv);
        }
        #pragma unroll
        for (int s = 0; s < 5; s++) {
            const float bh = fmaxf(0.0f, 1.0f - fabsf(hv - gridv[s]) * INV_H);
            phi_raw = fmaf(bh, w2r[s], phi_raw);
        }
    }

    const float q = sqrtf(d2) * INV_R;
    const float win = fmaf(q * q, fmaf(fmaf(-3.0f, q, 8.0f), q, -6.0f), 1.0f);
    return phi_raw * win;
}

__global__ __launch_bounds__(THREADS, 4)
void meshfree_kan_kernel(const float* __restrict__ x,
                         const float* __restrict__ nodes,
                         const float* __restrict__ W1a,
                         const float* __restrict__ W1b,
                         const float* __restrict__ W2,
                         const float* __restrict__ w,
                         float* __restrict__ out)
{
    __shared__ f4  s_Wp[HIDN][4];   // {W1a[h][0..4], W1b[h][0..4], W2[h][0..4], 0}
    __shared__ unsigned short s_buf[WARPS][BUFCAP];
    __shared__ int   s_cnt[WARPS];
    __shared__ float s_S[WARPS], s_Sw[WARPS];

    const int tid  = threadIdx.x;
    const int warp = tid >> 5;
    const int lane = tid & 31;
    const unsigned lmask = (1u << lane) - 1u;
    const int m0 = blockIdx.x * PPB;

    if (tid < HIDN * 16) {
        const int h = tid >> 4;
        const int e = tid & 15;
        float v = 0.0f;
        if (e < 5)       v = W1a[h * 5 + e];
        else if (e < 10) v = W1b[h * 5 + (e - 5)];
        else if (e < 15) v = W2 [h * 5 + (e - 10)];
        ((float*)s_Wp)[tid] = v;
    }

    const int p    = warp >> 1;        // point within block (0..3)
    const int half = warp & 1;         // node half-range
    const int m    = m0 + p;

    const float px = __ldg(x + 2 * m);
    const float py = __ldg(x + 2 * m + 1);

    // ---- Phase 1: scan own 512-node half, ballot-compact global indices ----
    int cnt = 0;
    const int b0 = half * NH;
    #pragma unroll 4
    for (int base = b0; base < b0 + NH; base += 32) {
        const int n = base + lane;
        const float2 nd = __ldg((const float2*)nodes + n);
        const float dx = px - nd.x;
        const float dy = py - nd.y;
        const float d2 = fmaf(dx, dx, dy * dy);
        const bool hit = (d2 <= R2_F);
        const unsigned msk = __ballot_sync(0xffffffffu, hit);
        if (hit) s_buf[warp][cnt + __popc(msk & lmask)] = (unsigned short)n;
        cnt += __popc(msk);
    }
    if (lane == 0) s_cnt[warp] = cnt;
    __syncthreads();

    // ---- Phase 2: joint consumption of the concatenated hit list ----
    const int c0 = s_cnt[2 * p];                  // warp0's count
    const int T  = c0 + s_cnt[2 * p + 1];

    float S = 0.0f, Sw = 0.0f;
    for (int j = half * 32 + lane; j < T; j += 64) {
        const int n = (j < c0) ? (int)s_buf[2 * p][j]
                               : (int)s_buf[2 * p + 1][j - c0];
        const float2 nd = __ldg((const float2*)nodes + n);
        const float phi = pair_phi(px - nd.x, py - nd.y, s_Wp);
        S  += phi;
        Sw  = fmaf(phi, __ldg(w + n), Sw);
    }

    // ---- Warp partial reduction ----
    #pragma unroll
    for (int o = 16; o > 0; o >>= 1) {
        S  += __shfl_xor_sync(0xffffffffu, S,  o);
        Sw += __shfl_xor_sync(0xffffffffu, Sw, o);
    }
    if (lane == 0) { s_S[warp] = S; s_Sw[warp] = Sw; }
    __syncthreads();

    // ---- Combine the two warp partials per point (fixed order) ----
    if (tid < PPB) {
        const float St  = s_S [2 * tid] + s_S [2 * tid + 1];
        const float Swt = s_Sw[2 * tid] + s_Sw[2 * tid + 1];
        out[m0 + tid] = Swt / (St + 1e-10f);
    }
}

extern "C" void kernel_launch(void* const* d_in, const int* in_sizes, int n_in,
                              void* d_out, int out_size)
{
    const float* x     = (const float*)d_in[0];   // [4096, 2]
    const float* nodes = (const float*)d_in[1];   // [1024, 2]
    const float* W1a   = (const float*)d_in[2];   // [8, 5]
    const float* W1b   = (const float*)d_in[3];   // [8, 5]
    const float* W2    = (const float*)d_in[4];   // [1, 40]
    const float* w     = (const float*)d_in[5];   // [1024, 1]
    float* out = (float*)d_out;                   // [4096, 1]

    meshfree_kan_kernel<<<BLOCKS, THREADS>>>(x, nodes, W1a, W1b, W2, w, out);
}